// round 11
// baseline (speedup 1.0000x reference)
#include <cuda_runtime.h>

#define NTHREADS 512
#define TN 32
#define N_DIM_ 2048

#define O_W1P 0
#define O_W2P 16384
#define O_CST 32768
#define O_H   40960
#define O_Y   49280
#define O_DEL 51456
#define SMEM_FLOATS 51464

typedef unsigned long long u64;

__device__ __forceinline__ void ffma2(u64 &d, u64 a, u64 b) {
    asm("fma.rn.f32x2 %0, %1, %2, %0;" : "+l"(d) : "l"(a), "l"(b));
}
__device__ __forceinline__ float2 up2(u64 v) {
    float2 r; asm("mov.b64 {%0, %1}, %2;" : "=f"(r.x), "=f"(r.y) : "l"(v)); return r;
}

extern __shared__ float smem[];

// One dynamics eval for the CTA's 32 nodes. Input state in Y. Returns raw MLP
// output (before +bb, *dlt) for node tid>>4, cols (tid&15)*4 .. +3.
__device__ __noinline__ float4 dyn_eval(int tid)
{
    __syncthreads();   // A: Y writes + prior reduce-reads complete

    // ---------- GEMM1: h = tanh(y @ W1a + cst) ----------
    {
        const float* Y   = smem + O_Y;
        const float* W   = smem + O_W1P;
        const float* CST = smem + O_CST;
        float*       H   = smem + O_H;
        const int nb = (tid >> 7) * 8;
        const int cg = tid & 127;

        float2 cv[8];                         // prefetch bias/static term
        #pragma unroll
        for (int n = 0; n < 8; n++)
            cv[n] = *(const float2*)(CST + (nb + n) * 256 + 2*cg);

        u64 acc[8][2];
        #pragma unroll
        for (int n = 0; n < 8; n++) { acc[n][0] = 0ULL; acc[n][1] = 0ULL; }

        #pragma unroll
        for (int j = 0; j < 16; j++) {
            ulonglong2 w0 = *(const ulonglong2*)(W + (2*j)   * 512 + 4*cg);
            ulonglong2 w1 = *(const ulonglong2*)(W + (2*j+1) * 512 + 4*cg);
            #pragma unroll
            for (int n = 0; n < 8; n++) {
                ulonglong2 a = *(const ulonglong2*)(Y + (nb + n) * 68 + 4*j);
                ffma2(acc[n][0], a.x, w0.x); ffma2(acc[n][1], a.x, w0.y);
                ffma2(acc[n][0], a.y, w1.x); ffma2(acc[n][1], a.y, w1.y);
            }
        }
        #pragma unroll
        for (int n = 0; n < 8; n++) {
            float2 a0 = up2(acc[n][0]), a1 = up2(acc[n][1]);
            float v0 = a0.x + a0.y + cv[n].x;
            float v1 = a1.x + a1.y + cv[n].y;
            // paired tanh: one RCP for two activations
            float u0 = __expf(-2.0f * fabsf(v0));
            float u1 = __expf(-2.0f * fabsf(v1));
            float d0 = 1.0f + u0, d1 = 1.0f + u1;
            float rr = __fdividef(1.0f, d0 * d1);
            float t0 = copysignf((1.0f - u0) * (rr * d1), v0);
            float t1 = copysignf((1.0f - u1) * (rr * d0), v1);
            *(float2*)(H + (nb + n) * 260 + 2*cg) = make_float2(t0, t1);
        }
    }
    __syncthreads();   // B: h visible

    // ---------- GEMM2: split-K=4, partials written IN-BAND (no barrier) ----
    {
        float* H = smem + O_H;
        const float* W = smem + O_W2P;
        const int sl = tid >> 7;
        const int ng = (tid >> 5) & 3;
        const int dg = tid & 31;
        const int nb = ng * 8;

        u64 acc[8][2];
        #pragma unroll
        for (int n = 0; n < 8; n++) { acc[n][0] = 0ULL; acc[n][1] = 0ULL; }

        #pragma unroll
        for (int j = 0; j < 16; j++) {
            const int kp0 = sl * 32 + 2*j;
            ulonglong2 w0 = *(const ulonglong2*)(W + kp0       * 128 + 4*dg);
            ulonglong2 w1 = *(const ulonglong2*)(W + (kp0 + 1) * 128 + 4*dg);
            #pragma unroll
            for (int n = 0; n < 8; n++) {
                ulonglong2 a = *(const ulonglong2*)(H + (nb + n) * 260 + sl*64 + 4*j);
                ffma2(acc[n][0], a.x, w0.x); ffma2(acc[n][1], a.x, w0.y);
                ffma2(acc[n][0], a.y, w1.x); ffma2(acc[n][1], a.y, w1.y);
            }
        }
        // This warp is the unique reader AND writer of H rows nb..nb+7,
        // cols [64*sl, 64*sl+64): loads above precede stores in program
        // order, so no barrier is needed before overwriting the band.
        #pragma unroll
        for (int n = 0; n < 8; n++) {
            float2 a0 = up2(acc[n][0]), a1 = up2(acc[n][1]);
            *(float2*)(H + (nb + n) * 260 + sl*64 + 2*dg)
                = make_float2(a0.x + a0.y, a1.x + a1.y);
        }
    }
    __syncthreads();   // D: partials visible

    // ---------- split-K reduce: node tid>>4, cols (tid&15)*4 ----------
    const float* Hs = smem + O_H;
    const int n_own = tid >> 4;
    const int d0i   = (tid & 15) * 4;
    float4 r = *(const float4*)(Hs + n_own * 260 + d0i);
    #pragma unroll
    for (int s = 1; s < 4; s++) {
        float4 v = *(const float4*)(Hs + n_own * 260 + s*64 + d0i);
        r.x += v.x; r.y += v.y; r.z += v.z; r.w += v.w;
    }
    return r;
}

__global__ void __launch_bounds__(NTHREADS, 1)
ode_v3(const float* __restrict__ gS,  const float* __restrict__ gT,
       const float* __restrict__ gPhi, const float* __restrict__ gB,
       const float* __restrict__ gW1, const float* __restrict__ gb1,
       const float* __restrict__ gW2, const float* __restrict__ gb2,
       float* __restrict__ gOut)
{
    const int tid   = threadIdx.x;
    const int sb    = blockIdx.x >> 6;
    const int tile  = blockIdx.x & 63;
    const int node0 = tile * TN;
    const int s_i   = sb >> 3, b_i = sb & 7;

    // ---- init: pair weights over k, stage W1p + Phi ----
    for (int i = tid; i < 8192; i += NTHREADS) {
        int fp = i >> 8, c = i & 255;
        *(float2*)(smem + O_W1P + fp * 512 + 2*c)
            = make_float2(gW1[(2*fp) * 256 + c], gW1[(2*fp+1) * 256 + c]);
    }
    for (int i = tid; i < 8192; i += NTHREADS) {
        int kp = i >> 6, d = i & 63;
        *(float2*)(smem + O_W2P + kp * 128 + 2*d)
            = make_float2(gW2[(2*kp) * 64 + d], gW2[(2*kp+1) * 64 + d]);
    }
    for (int i = tid; i < 8192; i += NTHREADS)
        smem[O_H + i] = gW1[64 * 256 + i];
    {
        const size_t pbase = ((size_t)sb * N_DIM_ + node0) * 32;
        for (int i = tid; i < TN * 32; i += NTHREADS)
            smem[O_Y + i] = gPhi[pbase + i];
    }
    if (tid < 8)
        smem[O_DEL + tid] = gT[sb * 9 + tid + 1] - gT[sb * 9 + tid];
    __syncthreads();

    // ---- CST = Phi @ W1p + b1 ----
    {
        const int n  = tid >> 4;
        const int c0 = (tid & 15) * 16;
        float acc[16];
        #pragma unroll
        for (int j = 0; j < 16; j++) acc[j] = gb1[c0 + j];
        const float* Ph = smem + O_Y + n * 32;
        const float* Ws = smem + O_H;
        #pragma unroll 4
        for (int q = 0; q < 32; q++) {
            float p = Ph[q];
            #pragma unroll
            for (int jj = 0; jj < 4; jj++) {
                float4 w = *(const float4*)(Ws + q * 256 + c0 + 4*jj);
                acc[4*jj]   += p * w.x; acc[4*jj+1] += p * w.y;
                acc[4*jj+2] += p * w.z; acc[4*jj+3] += p * w.w;
            }
        }
        __syncthreads();   // staging reads done
        #pragma unroll
        for (int jj = 0; jj < 4; jj++)
            *(float4*)(smem + O_CST + n * 256 + c0 + 4*jj)
                = make_float4(acc[4*jj], acc[4*jj+1], acc[4*jj+2], acc[4*jj+3]);
    }

    const int n_own = tid >> 4;
    const int d0    = (tid & 15) * 4;
    float x[4], bb[4];
    {
        const size_t g = ((size_t)sb * N_DIM_ + node0 + n_own) * 64 + d0;
        #pragma unroll
        for (int j = 0; j < 4; j++) {
            x[j]  = gS[g + j];
            bb[j] = gB[g + j] + gb2[d0 + j];
        }
        *(float4*)(smem + O_Y + n_own * 68 + d0) = make_float4(x[0], x[1], x[2], x[3]);
    }

    float accR[4], y[4];
    for (int kb = 0; kb < 8; kb++) {
        const float dlt = smem[O_DEL + kb];
        #pragma unroll 1
        for (int st = 0; st < 2; st++) {
            float4 r = dyn_eval(tid);
            {
                float k0 = (r.x + bb[0]) * dlt, k1 = (r.y + bb[1]) * dlt;
                float k2 = (r.z + bb[2]) * dlt, k3 = (r.w + bb[3]) * dlt;
                accR[0] = k0; accR[1] = k1; accR[2] = k2; accR[3] = k3;
                y[0] = x[0] + 0.25f*k0; y[1] = x[1] + 0.25f*k1;
                y[2] = x[2] + 0.25f*k2; y[3] = x[3] + 0.25f*k3;
                *(float4*)(smem + O_Y + n_own * 68 + d0) = make_float4(y[0], y[1], y[2], y[3]);
            }
            r = dyn_eval(tid);
            {
                float k0 = (r.x + bb[0]) * dlt, k1 = (r.y + bb[1]) * dlt;
                float k2 = (r.z + bb[2]) * dlt, k3 = (r.w + bb[3]) * dlt;
                accR[0] += 2.f*k0; accR[1] += 2.f*k1; accR[2] += 2.f*k2; accR[3] += 2.f*k3;
                y[0] = x[0] + 0.25f*k0; y[1] = x[1] + 0.25f*k1;
                y[2] = x[2] + 0.25f*k2; y[3] = x[3] + 0.25f*k3;
                *(float4*)(smem + O_Y + n_own * 68 + d0) = make_float4(y[0], y[1], y[2], y[3]);
            }
            r = dyn_eval(tid);
            {
                float k0 = (r.x + bb[0]) * dlt, k1 = (r.y + bb[1]) * dlt;
                float k2 = (r.z + bb[2]) * dlt, k3 = (r.w + bb[3]) * dlt;
                accR[0] += 2.f*k0; accR[1] += 2.f*k1; accR[2] += 2.f*k2; accR[3] += 2.f*k3;
                y[0] = x[0] + 0.5f*k0; y[1] = x[1] + 0.5f*k1;
                y[2] = x[2] + 0.5f*k2; y[3] = x[3] + 0.5f*k3;
                *(float4*)(smem + O_Y + n_own * 68 + d0) = make_float4(y[0], y[1], y[2], y[3]);
            }
            r = dyn_eval(tid);
            {
                float k0 = (r.x + bb[0]) * dlt, k1 = (r.y + bb[1]) * dlt;
                float k2 = (r.z + bb[2]) * dlt, k3 = (r.w + bb[3]) * dlt;
                const float c6 = 1.0f / 12.0f;
                x[0] += c6 * (accR[0] + k0); x[1] += c6 * (accR[1] + k1);
                x[2] += c6 * (accR[2] + k2); x[3] += c6 * (accR[3] + k3);
                *(float4*)(smem + O_Y + n_own * 68 + d0) = make_float4(x[0], x[1], x[2], x[3]);
                if (st == 1) {
                    const size_t o = ((size_t)(s_i * 64 + b_i * 8 + kb) * N_DIM_
                                      + node0 + n_own) * 64 + d0;
                    *(float4*)(gOut + o) = make_float4(x[0], x[1], x[2], x[3]);
                }
            }
        }
    }
}

extern "C" void kernel_launch(void* const* d_in, const int* in_sizes, int n_in,
                              void* d_out, int out_size) {
    (void)in_sizes; (void)n_in; (void)out_size;
    const float* s   = (const float*)d_in[0];
    const float* t   = (const float*)d_in[1];
    const float* Phi = (const float*)d_in[2];
    const float* b   = (const float*)d_in[3];
    const float* W1  = (const float*)d_in[4];
    const float* b1  = (const float*)d_in[5];
    const float* W2  = (const float*)d_in[6];
    const float* b2  = (const float*)d_in[7];
    const int smem_bytes = SMEM_FLOATS * (int)sizeof(float);
    cudaFuncSetAttribute(ode_v3, cudaFuncAttributeMaxDynamicSharedMemorySize, smem_bytes);
    ode_v3<<<1024, NTHREADS, smem_bytes>>>(s, t, Phi, b, W1, b1, W2, b2, (float*)d_out);
}

// round 14
// speedup vs baseline: 3.2396x; 3.2396x over previous
#include <cuda_runtime.h>
#include <cuda_bf16.h>

#define NTHREADS 512
#define TN 32
#define N_DIM_ 2048

// ---- SMEM byte offsets ----
#define O_W1H 0          // bf16 [64][264]
#define O_W1L 33792
#define O_W2H 67584      // bf16 [256][72]
#define O_W2L 104448
#define O_YH  141312     // bf16 [32][72]
#define O_YL  145920
#define O_HH  150528     // bf16 [32][264]  (init: f32 W1p staging 32KB spans HH..)
#define O_HL  167424
#define O_CST 184320     // f32 [32][260]
#define O_STG 217600     // f32 Phi staging [32][32]
#define O_DEL 221696     // f32 [8]
#define SMEM_BYTES 221760

typedef unsigned int u32;

__device__ __forceinline__ u32 cvsm(const void* p) {
    u32 a; asm("{.reg .u64 t; cvta.to.shared.u64 t,%1; cvt.u32.u64 %0,t;}"
               : "=r"(a) : "l"(p)); return a;
}
__device__ __forceinline__ void ldsm_x4(u32& r0, u32& r1, u32& r2, u32& r3, u32 a) {
    asm volatile("ldmatrix.sync.aligned.m8n8.x4.shared.b16 {%0,%1,%2,%3},[%4];"
                 : "=r"(r0), "=r"(r1), "=r"(r2), "=r"(r3) : "r"(a));
}
__device__ __forceinline__ void ldsm_x4t(u32& r0, u32& r1, u32& r2, u32& r3, u32 a) {
    asm volatile("ldmatrix.sync.aligned.m8n8.x4.trans.shared.b16 {%0,%1,%2,%3},[%4];"
                 : "=r"(r0), "=r"(r1), "=r"(r2), "=r"(r3) : "r"(a));
}
__device__ __forceinline__ void ldsm_x2t(u32& r0, u32& r1, u32 a) {
    asm volatile("ldmatrix.sync.aligned.m8n8.x2.trans.shared.b16 {%0,%1},[%2];"
                 : "=r"(r0), "=r"(r1) : "r"(a));
}
__device__ __forceinline__ void mma16816(float* c, u32 a0, u32 a1, u32 a2, u32 a3,
                                         u32 b0, u32 b1) {
    asm volatile("mma.sync.aligned.m16n8k16.row.col.f32.bf16.bf16.f32 "
                 "{%0,%1,%2,%3},{%4,%5,%6,%7},{%8,%9},{%0,%1,%2,%3};"
                 : "+f"(c[0]), "+f"(c[1]), "+f"(c[2]), "+f"(c[3])
                 : "r"(a0), "r"(a1), "r"(a2), "r"(a3), "r"(b0), "r"(b1));
}
__device__ __forceinline__ float tanh_fast(float x) {
    float u = __expf(-2.0f * fabsf(x));
    float t = __fdividef(1.0f - u, 1.0f + u);
    return copysignf(t, x);
}
union BU { __nv_bfloat162 b; u32 u; };
__device__ __forceinline__ void split2(float v0, float v1, u32& hi, u32& lo) {
    BU h; h.b = __floats2bfloat162_rn(v0, v1);
    BU l; l.b = __floats2bfloat162_rn(v0 - __bfloat162float(h.b.x),
                                      v1 - __bfloat162float(h.b.y));
    hi = h.u; lo = l.u;
}

extern __shared__ char smc[];

__global__ void __launch_bounds__(NTHREADS, 1)
ode_mma(const float* __restrict__ gS,  const float* __restrict__ gT,
        const float* __restrict__ gPhi, const float* __restrict__ gB,
        const float* __restrict__ gW1, const float* __restrict__ gb1,
        const float* __restrict__ gW2, const float* __restrict__ gb2,
        float* __restrict__ gOut)
{
    const int tid  = threadIdx.x;
    const int wid  = tid >> 5, lane = tid & 31;
    const int sb   = blockIdx.x >> 6;
    const int tile = blockIdx.x & 63;
    const int node0 = tile * TN;
    const int s_i = sb >> 3, b_i = sb & 7;
    const u32 smb = cvsm(smc);

    // ---------------- init phase 1: weight conversion + staging ----------------
    for (int i = tid; i < 64 * 256; i += NTHREADS) {        // W1 -> hi/lo [k][264]
        int k = i >> 8, n = i & 255;
        float v = gW1[k * 256 + n];
        __nv_bfloat16 h = __float2bfloat16(v);
        __nv_bfloat16 l = __float2bfloat16(v - __bfloat162float(h));
        *(__nv_bfloat16*)(smc + O_W1H + (k * 264 + n) * 2) = h;
        *(__nv_bfloat16*)(smc + O_W1L + (k * 264 + n) * 2) = l;
    }
    for (int i = tid; i < 256 * 64; i += NTHREADS) {        // W2 -> hi/lo [k][72]
        int k = i >> 6, d = i & 63;
        float v = gW2[k * 64 + d];
        __nv_bfloat16 h = __float2bfloat16(v);
        __nv_bfloat16 l = __float2bfloat16(v - __bfloat162float(h));
        *(__nv_bfloat16*)(smc + O_W2H + (k * 72 + d) * 2) = h;
        *(__nv_bfloat16*)(smc + O_W2L + (k * 72 + d) * 2) = l;
    }
    {   // W1p rows 64..95 staged as f32 [q][256] in H region
        float* wp = (float*)(smc + O_HH);
        for (int i = tid; i < 32 * 256; i += NTHREADS) wp[i] = gW1[64 * 256 + i];
        float* ph = (float*)(smc + O_STG);
        const size_t pbase = ((size_t)sb * N_DIM_ + node0) * 32;
        for (int i = tid; i < TN * 32; i += NTHREADS) ph[i] = gPhi[pbase + i];
    }
    if (tid < 8)
        ((float*)(smc + O_DEL))[tid] = gT[sb * 9 + tid + 1] - gT[sb * 9 + tid];
    __syncthreads();

    // ---------------- init phase 2: CST = Phi @ W1p + b1  (f32 [n][260]) ------
    {
        const int n  = tid >> 4;
        const int c0 = (tid & 15) * 16;
        float acc[16];
        #pragma unroll
        for (int j = 0; j < 16; j++) acc[j] = gb1[c0 + j];
        const float* Ph = (const float*)(smc + O_STG) + n * 32;
        const float* Ws = (const float*)(smc + O_HH);
        #pragma unroll 4
        for (int q = 0; q < 32; q++) {
            float p = Ph[q];
            #pragma unroll
            for (int jj = 0; jj < 4; jj++) {
                float4 w = *(const float4*)(Ws + q * 256 + c0 + 4 * jj);
                acc[4*jj]   += p * w.x; acc[4*jj+1] += p * w.y;
                acc[4*jj+2] += p * w.z; acc[4*jj+3] += p * w.w;
            }
        }
        float* cst = (float*)(smc + O_CST);
        #pragma unroll
        for (int jj = 0; jj < 4; jj++)
            *(float4*)(cst + n * 260 + c0 + 4 * jj)
                = make_float4(acc[4*jj], acc[4*jj+1], acc[4*jj+2], acc[4*jj+3]);
    }

    // ---------------- per-thread RK4 state in C2-fragment layout ----------------
    const int g  = lane >> 2, tq = lane & 3;
    const int m0 = (wid & 1) * 16;
    const int n0g2 = (wid >> 1) * 8;          // GEMM2 col block (covers 64 d-cols)
    const int r0 = m0 + g, r1 = m0 + g + 8;
    const int c0d = n0g2 + 2 * tq;
    float x[4], bb[4];
    {
        const size_t ga = ((size_t)sb * N_DIM_ + node0 + r0) * 64 + c0d;
        const size_t gbA = ((size_t)sb * N_DIM_ + node0 + r1) * 64 + c0d;
        x[0] = gS[ga]; x[1] = gS[ga + 1]; x[2] = gS[gbA]; x[3] = gS[gbA + 1];
        bb[0] = gB[ga]      + gb2[c0d];
        bb[1] = gB[ga + 1]  + gb2[c0d + 1];
        bb[2] = gB[gbA]     + gb2[c0d];
        bb[3] = gB[gbA + 1] + gb2[c0d + 1];
        u32 h0, l0, h1, l1;
        split2(x[0], x[1], h0, l0); split2(x[2], x[3], h1, l1);
        *(u32*)(smc + O_YH + (r0 * 72 + c0d) * 2) = h0;
        *(u32*)(smc + O_YL + (r0 * 72 + c0d) * 2) = l0;
        *(u32*)(smc + O_YH + (r1 * 72 + c0d) * 2) = h1;
        *(u32*)(smc + O_YL + (r1 * 72 + c0d) * 2) = l1;
    }
    __syncthreads();

    // ldmatrix lane-address components
    const int lq  = lane >> 3;          // quadrant
    const int lr  = lane & 7;           // row in quadrant
    const int qm  = (lq & 1) * 8;       // row-block select
    const int qk  = (lq >> 1) * 8;      // col-block select
    const int nc1 = (wid >> 1) * 32;    // GEMM1 col block (32 cols -> full 256)
    const int b2r = ((lane >> 3) & 1) * 8 + lr;   // x2.trans rows (lanes 0-15)

    float accR[4], kk[4];
    const float* cst = (const float*)(smc + O_CST);

    for (int kb = 0; kb < 8; kb++) {
        const float dlt = ((const float*)(smc + O_DEL))[kb];
        #pragma unroll 1
        for (int ev = 0; ev < 8; ev++) {     // 2 RK4 steps x 4 stages
            const int st = ev & 3;
            // ================= GEMM1: C1[32,256] = Y @ W1a =================
            float c1[4][4];
            #pragma unroll
            for (int nt = 0; nt < 4; nt++)
                #pragma unroll
                for (int j = 0; j < 4; j++) c1[nt][j] = 0.f;
            #pragma unroll
            for (int kt = 0; kt < 4; kt++) {
                const int k0 = kt * 16;
                u32 aoff = ((u32)((m0 + qm + lr) * 72 + k0 + qk)) * 2;
                u32 ah0, ah1, ah2, ah3, al0, al1, al2, al3;
                ldsm_x4(ah0, ah1, ah2, ah3, smb + O_YH + aoff);
                ldsm_x4(al0, al1, al2, al3, smb + O_YL + aoff);
                #pragma unroll
                for (int half = 0; half < 2; half++) {
                    u32 boff = ((u32)((k0 + qm + lr) * 264 + nc1 + 16 * half + qk)) * 2;
                    u32 bh0, bh1, bh2, bh3, bl0, bl1, bl2, bl3;
                    ldsm_x4t(bh0, bh1, bh2, bh3, smb + O_W1H + boff);
                    ldsm_x4t(bl0, bl1, bl2, bl3, smb + O_W1L + boff);
                    float* ca = c1[2 * half];
                    float* cb = c1[2 * half + 1];
                    mma16816(ca, ah0, ah1, ah2, ah3, bh0, bh1);
                    mma16816(ca, al0, al1, al2, al3, bh0, bh1);
                    mma16816(ca, ah0, ah1, ah2, ah3, bl0, bl1);
                    mma16816(cb, ah0, ah1, ah2, ah3, bh2, bh3);
                    mma16816(cb, al0, al1, al2, al3, bh2, bh3);
                    mma16816(cb, ah0, ah1, ah2, ah3, bl2, bl3);
                }
            }
            // epilogue: h = tanh(C1 + cst) -> H hi/lo (4 n8-tiles per warp)
            #pragma unroll
            for (int nt = 0; nt < 4; nt++) {
                float* cc = c1[nt];
                const int col = nc1 + 8 * nt + 2 * tq;
                float2 cA = *(const float2*)(cst + r0 * 260 + col);
                float2 cB = *(const float2*)(cst + r1 * 260 + col);
                float t0 = tanh_fast(cc[0] + cA.x);
                float t1 = tanh_fast(cc[1] + cA.y);
                float t2 = tanh_fast(cc[2] + cB.x);
                float t3 = tanh_fast(cc[3] + cB.y);
                u32 h0, l0, h1, l1;
                split2(t0, t1, h0, l0); split2(t2, t3, h1, l1);
                *(u32*)(smc + O_HH + (r0 * 264 + col) * 2) = h0;
                *(u32*)(smc + O_HL + (r0 * 264 + col) * 2) = l0;
                *(u32*)(smc + O_HH + (r1 * 264 + col) * 2) = h1;
                *(u32*)(smc + O_HL + (r1 * 264 + col) * 2) = l1;
            }
            __syncthreads();   // H ready (also: Y reads of this eval complete)

            // ================= GEMM2: C2[32,64] = H @ W2 =================
            float c2[4] = {0.f, 0.f, 0.f, 0.f};
            #pragma unroll 4
            for (int kt = 0; kt < 16; kt++) {
                const int k0 = kt * 16;
                u32 aoff = ((u32)((m0 + qm + lr) * 264 + k0 + qk)) * 2;
                u32 ah0, ah1, ah2, ah3, al0, al1, al2, al3;
                ldsm_x4(ah0, ah1, ah2, ah3, smb + O_HH + aoff);
                ldsm_x4(al0, al1, al2, al3, smb + O_HL + aoff);
                u32 boff = ((u32)((k0 + b2r) * 72 + n0g2)) * 2;
                u32 bh0, bh1, bl0, bl1;
                ldsm_x2t(bh0, bh1, smb + O_W2H + boff);
                ldsm_x2t(bl0, bl1, smb + O_W2L + boff);
                mma16816(c2, ah0, ah1, ah2, ah3, bh0, bh1);
                mma16816(c2, al0, al1, al2, al3, bh0, bh1);
                mma16816(c2, ah0, ah1, ah2, ah3, bl0, bl1);
            }
            // k = (C2 + bb) * dlt ; RK4 update
            #pragma unroll
            for (int j = 0; j < 4; j++) kk[j] = (c2[j] + bb[j]) * dlt;
            float y[4];
            if (st == 0) {
                #pragma unroll
                for (int j = 0; j < 4; j++) { accR[j] = kk[j]; y[j] = x[j] + 0.25f * kk[j]; }
            } else if (st == 1) {
                #pragma unroll
                for (int j = 0; j < 4; j++) { accR[j] += 2.f * kk[j]; y[j] = x[j] + 0.25f * kk[j]; }
            } else if (st == 2) {
                #pragma unroll
                for (int j = 0; j < 4; j++) { accR[j] += 2.f * kk[j]; y[j] = x[j] + 0.5f * kk[j]; }
            } else {
                #pragma unroll
                for (int j = 0; j < 4; j++) { accR[j] += kk[j]; x[j] += (1.0f / 12.0f) * accR[j]; y[j] = x[j]; }
            }
            {
                u32 h0, l0, h1, l1;
                split2(y[0], y[1], h0, l0); split2(y[2], y[3], h1, l1);
                *(u32*)(smc + O_YH + (r0 * 72 + c0d) * 2) = h0;
                *(u32*)(smc + O_YL + (r0 * 72 + c0d) * 2) = l0;
                *(u32*)(smc + O_YH + (r1 * 72 + c0d) * 2) = h1;
                *(u32*)(smc + O_YL + (r1 * 72 + c0d) * 2) = l1;
            }
            if (ev == 7) {   // end of block-step: write output state
                const size_t ob = ((size_t)(s_i * 64 + b_i * 8 + kb) * N_DIM_ + node0);
                *(float2*)(gOut + (ob + r0) * 64 + c0d) = make_float2(x[0], x[1]);
                *(float2*)(gOut + (ob + r1) * 64 + c0d) = make_float2(x[2], x[3]);
            }
            __syncthreads();   // Y ready for next eval (and H reads complete)
        }
    }
}

extern "C" void kernel_launch(void* const* d_in, const int* in_sizes, int n_in,
                              void* d_out, int out_size) {
    (void)in_sizes; (void)n_in; (void)out_size;
    const float* s   = (const float*)d_in[0];
    const float* t   = (const float*)d_in[1];
    const float* Phi = (const float*)d_in[2];
    const float* b   = (const float*)d_in[3];
    const float* W1  = (const float*)d_in[4];
    const float* b1  = (const float*)d_in[5];
    const float* W2  = (const float*)d_in[6];
    const float* b2  = (const float*)d_in[7];
    cudaFuncSetAttribute(ode_mma, cudaFuncAttributeMaxDynamicSharedMemorySize, SMEM_BYTES);
    ode_mma<<<1024, NTHREADS, SMEM_BYTES>>>(s, t, Phi, b, W1, b1, W2, b2, (float*)d_out);
}

// round 15
// speedup vs baseline: 3.9795x; 1.2284x over previous
#include <cuda_runtime.h>
#include <cuda_fp16.h>

#define NTHREADS 512
#define TN 64
#define N_DIM_ 2048

// ---- SMEM byte offsets ----
#define O_W1H 0          // fp16 [64 k][264]  W1a          33792
#define O_W2H 33792      // fp16 [256 k][72]  W2           36864
#define O_YH  70656      // fp16 [64 n][72]                 9216
#define O_YL  79872      // fp16 [64 n][72]                 9216
#define O_HH  89088      // fp16 [64 n][264]               33792  (init overlay: f32 W1p 32KB)
#define O_HL  122880     // fp16 [64 n][264]               33792  (init overlay: f32 Phi 8KB)
#define O_CST 156672     // f32  [64 n][260]               66560
#define O_DEL 223232     // f32 [8]
#define SMEM_BYTES 223264

typedef unsigned int u32;

__device__ __forceinline__ u32 cvsm(const void* p) {
    u32 a; asm("{.reg .u64 t; cvta.to.shared.u64 t,%1; cvt.u32.u64 %0,t;}"
               : "=r"(a) : "l"(p)); return a;
}
__device__ __forceinline__ void ldsm_x4(u32& r0, u32& r1, u32& r2, u32& r3, u32 a) {
    asm volatile("ldmatrix.sync.aligned.m8n8.x4.shared.b16 {%0,%1,%2,%3},[%4];"
                 : "=r"(r0), "=r"(r1), "=r"(r2), "=r"(r3) : "r"(a));
}
__device__ __forceinline__ void ldsm_x4t(u32& r0, u32& r1, u32& r2, u32& r3, u32 a) {
    asm volatile("ldmatrix.sync.aligned.m8n8.x4.trans.shared.b16 {%0,%1,%2,%3},[%4];"
                 : "=r"(r0), "=r"(r1), "=r"(r2), "=r"(r3) : "r"(a));
}
__device__ __forceinline__ void mma16816(float* c, u32 a0, u32 a1, u32 a2, u32 a3,
                                         u32 b0, u32 b1) {
    asm volatile("mma.sync.aligned.m16n8k16.row.col.f32.f16.f16.f32 "
                 "{%0,%1,%2,%3},{%4,%5,%6,%7},{%8,%9},{%0,%1,%2,%3};"
                 : "+f"(c[0]), "+f"(c[1]), "+f"(c[2]), "+f"(c[3])
                 : "r"(a0), "r"(a1), "r"(a2), "r"(a3), "r"(b0), "r"(b1));
}
__device__ __forceinline__ float tanh_fast(float x) {
    float u = __expf(-2.0f * fabsf(x));
    float t = __fdividef(1.0f - u, 1.0f + u);
    return copysignf(t, x);
}
union HU { __half2 h; u32 u; };
__device__ __forceinline__ void split2(float v0, float v1, u32& hi, u32& lo) {
    HU h; h.h = __floats2half2_rn(v0, v1);
    HU l; l.h = __floats2half2_rn(v0 - __half2float(__low2half(h.h)),
                                  v1 - __half2float(__high2half(h.h)));
    hi = h.u; lo = l.u;
}

extern __shared__ char smc[];

__global__ void __launch_bounds__(NTHREADS, 1)
ode_mma64(const float* __restrict__ gS,  const float* __restrict__ gT,
          const float* __restrict__ gPhi, const float* __restrict__ gB,
          const float* __restrict__ gW1, const float* __restrict__ gb1,
          const float* __restrict__ gW2, const float* __restrict__ gb2,
          float* __restrict__ gOut)
{
    const int tid  = threadIdx.x;
    const int wid  = tid >> 5, lane = tid & 31;
    const int sb   = blockIdx.x >> 5;        // 16 (s,b)
    const int tile = blockIdx.x & 31;        // 32 tiles of 64 nodes
    const int node0 = tile * TN;
    const int s_i = sb >> 3, b_i = sb & 7;
    const u32 smb = cvsm(smc);

    // ---------------- init phase 1: weight conversion + staging ----------------
    for (int i = tid; i < 64 * 256; i += NTHREADS) {        // W1a -> fp16 [k][264]
        int k = i >> 8, n = i & 255;
        *(__half*)(smc + O_W1H + (k * 264 + n) * 2) = __float2half(gW1[k * 256 + n]);
    }
    for (int i = tid; i < 256 * 64; i += NTHREADS) {        // W2 -> fp16 [k][72]
        int k = i >> 6, d = i & 63;
        *(__half*)(smc + O_W2H + (k * 72 + d) * 2) = __float2half(gW2[k * 64 + d]);
    }
    {   // W1p rows 64..95 staged as f32 [q][256] at O_HH; Phi f32 [64][32] at O_HL
        float* wp = (float*)(smc + O_HH);
        for (int i = tid; i < 32 * 256; i += NTHREADS) wp[i] = gW1[64 * 256 + i];
        float* ph = (float*)(smc + O_HL);
        const size_t pbase = ((size_t)sb * N_DIM_ + node0) * 32;
        for (int i = tid; i < TN * 32; i += NTHREADS) ph[i] = gPhi[pbase + i];
    }
    if (tid < 8)
        ((float*)(smc + O_DEL))[tid] = gT[sb * 9 + tid + 1] - gT[sb * 9 + tid];
    __syncthreads();

    // ---------------- init phase 2: CST = Phi @ W1p + b1  (f32 [64][260]) ------
    {
        const int n    = tid >> 3;           // 64 nodes, 8 threads each
        const int cgrp = tid & 7;            // 32 cols per thread, 2 chunks of 16
        const float* Ph = (const float*)(smc + O_HL) + n * 32;
        const float* Ws = (const float*)(smc + O_HH);
        float* cst = (float*)(smc + O_CST);
        #pragma unroll
        for (int ch = 0; ch < 2; ch++) {
            const int c0 = cgrp * 32 + ch * 16;
            float acc[16];
            #pragma unroll
            for (int j = 0; j < 16; j++) acc[j] = gb1[c0 + j];
            #pragma unroll 4
            for (int q = 0; q < 32; q++) {
                float p = Ph[q];
                #pragma unroll
                for (int jj = 0; jj < 4; jj++) {
                    float4 w = *(const float4*)(Ws + q * 256 + c0 + 4 * jj);
                    acc[4*jj]   += p * w.x; acc[4*jj+1] += p * w.y;
                    acc[4*jj+2] += p * w.z; acc[4*jj+3] += p * w.w;
                }
            }
            #pragma unroll
            for (int jj = 0; jj < 4; jj++)
                *(float4*)(cst + n * 260 + c0 + 4 * jj)
                    = make_float4(acc[4*jj], acc[4*jj+1], acc[4*jj+2], acc[4*jj+3]);
        }
    }

    // ---------------- warp / thread tile mapping ----------------
    const int mb = wid & 3;                 // 4 m-blocks of 16 nodes
    const int nb = wid >> 2;                // 4 n-blocks
    const int g  = lane >> 2, tq = lane & 3;
    const int r0 = mb * 16 + g, r1 = r0 + 8;
    const int c0 = nb * 16 + 2 * tq;        // GEMM2 col (tiles at c0 and c0+8)
    const int lq = lane >> 3, lr = lane & 7;
    const int qm = (lq & 1) * 8, qk = (lq >> 1) * 8;

    // ---------------- per-thread RK4 state (C2-fragment layout) ----------------
    float x[8], bb[8];
    {
        const size_t gr0 = ((size_t)sb * N_DIM_ + node0 + r0) * 64;
        const size_t gr1 = ((size_t)sb * N_DIM_ + node0 + r1) * 64;
        #pragma unroll
        for (int t = 0; t < 2; t++) {
            const int c = c0 + 8 * t;
            x[t*4+0] = gS[gr0 + c]; x[t*4+1] = gS[gr0 + c + 1];
            x[t*4+2] = gS[gr1 + c]; x[t*4+3] = gS[gr1 + c + 1];
            bb[t*4+0] = gB[gr0 + c]     + gb2[c];
            bb[t*4+1] = gB[gr0 + c + 1] + gb2[c + 1];
            bb[t*4+2] = gB[gr1 + c]     + gb2[c];
            bb[t*4+3] = gB[gr1 + c + 1] + gb2[c + 1];
            u32 h0, l0, h1, l1;
            split2(x[t*4+0], x[t*4+1], h0, l0);
            split2(x[t*4+2], x[t*4+3], h1, l1);
            *(u32*)(smc + O_YH + (r0 * 72 + c) * 2) = h0;
            *(u32*)(smc + O_YL + (r0 * 72 + c) * 2) = l0;
            *(u32*)(smc + O_YH + (r1 * 72 + c) * 2) = h1;
            *(u32*)(smc + O_YL + (r1 * 72 + c) * 2) = l1;
        }
    }
    __syncthreads();   // CST + initial Y ready; staging region dead

    const float* cst = (const float*)(smc + O_CST);
    float accR[8], kk[8];

    for (int kb = 0; kb < 8; kb++) {
        const float dlt = ((const float*)(smc + O_DEL))[kb];
        #pragma unroll 1
        for (int ev = 0; ev < 8; ev++) {
            const int st = ev & 3;
            // ========== GEMM1: C1[64,256] = Y @ W1a, two n32 passes ==========
            #pragma unroll
            for (int pass = 0; pass < 2; pass++) {
                float c1[4][4];
                #pragma unroll
                for (int nt = 0; nt < 4; nt++)
                    #pragma unroll
                    for (int j = 0; j < 4; j++) c1[nt][j] = 0.f;
                #pragma unroll
                for (int kt = 0; kt < 4; kt++) {
                    const int k0 = kt * 16;
                    u32 aoff = ((u32)((mb * 16 + qm + lr) * 72 + k0 + qk)) * 2;
                    u32 ah0, ah1, ah2, ah3, al0, al1, al2, al3;
                    ldsm_x4(ah0, ah1, ah2, ah3, smb + O_YH + aoff);
                    ldsm_x4(al0, al1, al2, al3, smb + O_YL + aoff);
                    #pragma unroll
                    for (int half = 0; half < 2; half++) {
                        u32 boff = ((u32)((k0 + qm + lr) * 264
                                    + nb * 64 + pass * 32 + 16 * half + qk)) * 2;
                        u32 bh0, bh1, bh2, bh3;
                        ldsm_x4t(bh0, bh1, bh2, bh3, smb + O_W1H + boff);
                        float* ca = c1[2 * half];
                        float* cb = c1[2 * half + 1];
                        mma16816(ca, ah0, ah1, ah2, ah3, bh0, bh1);
                        mma16816(ca, al0, al1, al2, al3, bh0, bh1);
                        mma16816(cb, ah0, ah1, ah2, ah3, bh2, bh3);
                        mma16816(cb, al0, al1, al2, al3, bh2, bh3);
                    }
                }
                // epilogue: h = tanh(C1 + cst) -> H hi/lo
                #pragma unroll
                for (int nt = 0; nt < 4; nt++) {
                    float* cc = c1[nt];
                    const int col = nb * 64 + pass * 32 + 8 * nt + 2 * tq;
                    float2 cA = *(const float2*)(cst + r0 * 260 + col);
                    float2 cB = *(const float2*)(cst + r1 * 260 + col);
                    float t0 = tanh_fast(cc[0] + cA.x);
                    float t1 = tanh_fast(cc[1] + cA.y);
                    float t2 = tanh_fast(cc[2] + cB.x);
                    float t3 = tanh_fast(cc[3] + cB.y);
                    u32 h0, l0, h1, l1;
                    split2(t0, t1, h0, l0); split2(t2, t3, h1, l1);
                    *(u32*)(smc + O_HH + (r0 * 264 + col) * 2) = h0;
                    *(u32*)(smc + O_HL + (r0 * 264 + col) * 2) = l0;
                    *(u32*)(smc + O_HH + (r1 * 264 + col) * 2) = h1;
                    *(u32*)(smc + O_HL + (r1 * 264 + col) * 2) = l1;
                }
            }
            __syncthreads();   // H ready; Y reads of this eval complete

            // ========== GEMM2: C2[64,64] = H @ W2 ==========
            float c2[2][4];
            #pragma unroll
            for (int t = 0; t < 2; t++)
                #pragma unroll
                for (int j = 0; j < 4; j++) c2[t][j] = 0.f;
            #pragma unroll 4
            for (int kt = 0; kt < 16; kt++) {
                const int k0 = kt * 16;
                u32 aoff = ((u32)((mb * 16 + qm + lr) * 264 + k0 + qk)) * 2;
                u32 ah0, ah1, ah2, ah3, al0, al1, al2, al3;
                ldsm_x4(ah0, ah1, ah2, ah3, smb + O_HH + aoff);
                ldsm_x4(al0, al1, al2, al3, smb + O_HL + aoff);
                u32 boff = ((u32)((k0 + qm + lr) * 72 + nb * 16 + qk)) * 2;
                u32 bh0, bh1, bh2, bh3;
                ldsm_x4t(bh0, bh1, bh2, bh3, smb + O_W2H + boff);
                mma16816(c2[0], ah0, ah1, ah2, ah3, bh0, bh1);
                mma16816(c2[0], al0, al1, al2, al3, bh0, bh1);
                mma16816(c2[1], ah0, ah1, ah2, ah3, bh2, bh3);
                mma16816(c2[1], al0, al1, al2, al3, bh2, bh3);
            }
            // ========== RK4 update ==========
            #pragma unroll
            for (int t = 0; t < 2; t++)
                #pragma unroll
                for (int j = 0; j < 4; j++)
                    kk[t*4+j] = (c2[t][j] + bb[t*4+j]) * dlt;
            float y[8];
            if (st == 0) {
                #pragma unroll
                for (int j = 0; j < 8; j++) { accR[j] = kk[j]; y[j] = x[j] + 0.25f * kk[j]; }
            } else if (st == 1) {
                #pragma unroll
                for (int j = 0; j < 8; j++) { accR[j] += 2.f * kk[j]; y[j] = x[j] + 0.25f * kk[j]; }
            } else if (st == 2) {
                #pragma unroll
                for (int j = 0; j < 8; j++) { accR[j] += 2.f * kk[j]; y[j] = x[j] + 0.5f * kk[j]; }
            } else {
                #pragma unroll
                for (int j = 0; j < 8; j++) { accR[j] += kk[j]; x[j] += (1.0f / 12.0f) * accR[j]; y[j] = x[j]; }
            }
            #pragma unroll
            for (int t = 0; t < 2; t++) {
                const int c = c0 + 8 * t;
                u32 h0, l0, h1, l1;
                split2(y[t*4+0], y[t*4+1], h0, l0);
                split2(y[t*4+2], y[t*4+3], h1, l1);
                *(u32*)(smc + O_YH + (r0 * 72 + c) * 2) = h0;
                *(u32*)(smc + O_YL + (r0 * 72 + c) * 2) = l0;
                *(u32*)(smc + O_YH + (r1 * 72 + c) * 2) = h1;
                *(u32*)(smc + O_YL + (r1 * 72 + c) * 2) = l1;
            }
            if (ev == 7) {   // end of block-step: write output state
                const size_t ob = ((size_t)(s_i * 64 + b_i * 8 + kb) * N_DIM_ + node0);
                #pragma unroll
                for (int t = 0; t < 2; t++) {
                    const int c = c0 + 8 * t;
                    *(float2*)(gOut + (ob + r0) * 64 + c) = make_float2(x[t*4+0], x[t*4+1]);
                    *(float2*)(gOut + (ob + r1) * 64 + c) = make_float2(x[t*4+2], x[t*4+3]);
                }
            }
            __syncthreads();   // Y ready for next eval; H reads complete
        }
    }
}

extern "C" void kernel_launch(void* const* d_in, const int* in_sizes, int n_in,
                              void* d_out, int out_size) {
    (void)in_sizes; (void)n_in; (void)out_size;
    const float* s   = (const float*)d_in[0];
    const float* t   = (const float*)d_in[1];
    const float* Phi = (const float*)d_in[2];
    const float* b   = (const float*)d_in[3];
    const float* W1  = (const float*)d_in[4];
    const float* b1  = (const float*)d_in[5];
    const float* W2  = (const float*)d_in[6];
    const float* b2  = (const float*)d_in[7];
    cudaFuncSetAttribute(ode_mma64, cudaFuncAttributeMaxDynamicSharedMemorySize, SMEM_BYTES);
    ode_mma64<<<512, NTHREADS, SMEM_BYTES>>>(s, t, Phi, b, W1, b1, W2, b2, (float*)d_out);
}

// round 16
// speedup vs baseline: 5.0852x; 1.2778x over previous
#include <cuda_runtime.h>
#include <cuda_fp16.h>

#define NTHREADS 512
#define TN 64
#define N_DIM_ 2048

// ---- SMEM byte offsets ----
#define O_W1H 0          // fp16 [64 k][264]  W1a          33792
#define O_W2H 33792      // fp16 [256 k][72]  W2           36864
#define O_YH  70656      // fp16 [64 n][72]                 9216  (init overlay: f32 Phi 8KB)
#define O_HH  79872      // fp16 [64 n][264]               33792  (init overlay: f32 W1p 32KB)
#define O_CST 113664     // f32  [64 n][260]               66560
#define O_DEL 180224     // f32 [8]
#define SMEM_BYTES 180256

typedef unsigned int u32;

__device__ __forceinline__ u32 cvsm(const void* p) {
    u32 a; asm("{.reg .u64 t; cvta.to.shared.u64 t,%1; cvt.u32.u64 %0,t;}"
               : "=r"(a) : "l"(p)); return a;
}
__device__ __forceinline__ void ldsm_x4(u32& r0, u32& r1, u32& r2, u32& r3, u32 a) {
    asm volatile("ldmatrix.sync.aligned.m8n8.x4.shared.b16 {%0,%1,%2,%3},[%4];"
                 : "=r"(r0), "=r"(r1), "=r"(r2), "=r"(r3) : "r"(a));
}
__device__ __forceinline__ void ldsm_x4t(u32& r0, u32& r1, u32& r2, u32& r3, u32 a) {
    asm volatile("ldmatrix.sync.aligned.m8n8.x4.trans.shared.b16 {%0,%1,%2,%3},[%4];"
                 : "=r"(r0), "=r"(r1), "=r"(r2), "=r"(r3) : "r"(a));
}
__device__ __forceinline__ void mma16816(float* c, u32 a0, u32 a1, u32 a2, u32 a3,
                                         u32 b0, u32 b1) {
    asm volatile("mma.sync.aligned.m16n8k16.row.col.f32.f16.f16.f32 "
                 "{%0,%1,%2,%3},{%4,%5,%6,%7},{%8,%9},{%0,%1,%2,%3};"
                 : "+f"(c[0]), "+f"(c[1]), "+f"(c[2]), "+f"(c[3])
                 : "r"(a0), "r"(a1), "r"(a2), "r"(a3), "r"(b0), "r"(b1));
}
__device__ __forceinline__ float tanh_fast(float x) {
    float u = __expf(-2.0f * fabsf(x));
    float t = __fdividef(1.0f - u, 1.0f + u);
    return copysignf(t, x);
}
union HU { __half2 h; u32 u; };
__device__ __forceinline__ u32 pk16(float v0, float v1) {
    HU h; h.h = __floats2half2_rn(v0, v1); return h.u;
}

extern __shared__ char smc[];

__global__ void __launch_bounds__(NTHREADS, 1)
ode_f16s(const float* __restrict__ gS,  const float* __restrict__ gT,
         const float* __restrict__ gPhi, const float* __restrict__ gB,
         const float* __restrict__ gW1, const float* __restrict__ gb1,
         const float* __restrict__ gW2, const float* __restrict__ gb2,
         float* __restrict__ gOut)
{
    const int tid  = threadIdx.x;
    const int wid  = tid >> 5, lane = tid & 31;
    const int sb   = blockIdx.x >> 5;        // 16 (s,b)
    const int tile = blockIdx.x & 31;        // 32 tiles of 64 nodes
    const int node0 = tile * TN;
    const int s_i = sb >> 3, b_i = sb & 7;
    const u32 smb = cvsm(smc);

    // ---------------- init phase 1: weight conversion + staging ----------------
    for (int i = tid; i < 64 * 256; i += NTHREADS) {        // W1a -> fp16 [k][264]
        int k = i >> 8, n = i & 255;
        *(__half*)(smc + O_W1H + (k * 264 + n) * 2) = __float2half(gW1[k * 256 + n]);
    }
    for (int i = tid; i < 256 * 64; i += NTHREADS) {        // W2 -> fp16 [k][72]
        int k = i >> 6, d = i & 63;
        *(__half*)(smc + O_W2H + (k * 72 + d) * 2) = __float2half(gW2[k * 64 + d]);
    }
    {   // W1p rows 64..95 staged f32 [q][256] at O_HH; Phi f32 [64][32] at O_YH
        float* wp = (float*)(smc + O_HH);
        for (int i = tid; i < 32 * 256; i += NTHREADS) wp[i] = gW1[64 * 256 + i];
        float* ph = (float*)(smc + O_YH);
        const size_t pbase = ((size_t)sb * N_DIM_ + node0) * 32;
        for (int i = tid; i < TN * 32; i += NTHREADS) ph[i] = gPhi[pbase + i];
    }
    if (tid < 8)
        ((float*)(smc + O_DEL))[tid] = gT[sb * 9 + tid + 1] - gT[sb * 9 + tid];
    __syncthreads();

    // ---------------- init phase 2: CST = Phi @ W1p + b1  (f32 [64][260]) ------
    {
        const int n    = tid >> 3;           // 64 nodes, 8 threads each
        const int cgrp = tid & 7;
        const float* Ph = (const float*)(smc + O_YH) + n * 32;
        const float* Ws = (const float*)(smc + O_HH);
        float* cst = (float*)(smc + O_CST);
        #pragma unroll
        for (int ch = 0; ch < 2; ch++) {
            const int c0 = cgrp * 32 + ch * 16;
            float acc[16];
            #pragma unroll
            for (int j = 0; j < 16; j++) acc[j] = gb1[c0 + j];
            #pragma unroll 4
            for (int q = 0; q < 32; q++) {
                float p = Ph[q];
                #pragma unroll
                for (int jj = 0; jj < 4; jj++) {
                    float4 w = *(const float4*)(Ws + q * 256 + c0 + 4 * jj);
                    acc[4*jj]   += p * w.x; acc[4*jj+1] += p * w.y;
                    acc[4*jj+2] += p * w.z; acc[4*jj+3] += p * w.w;
                }
            }
            #pragma unroll
            for (int jj = 0; jj < 4; jj++)
                *(float4*)(cst + n * 260 + c0 + 4 * jj)
                    = make_float4(acc[4*jj], acc[4*jj+1], acc[4*jj+2], acc[4*jj+3]);
        }
    }
    __syncthreads();   // CST done; Phi/W1p staging dead

    // ---------------- warp / thread tile mapping ----------------
    const int mb = wid & 3;                 // 4 m-blocks of 16 nodes
    const int nb = wid >> 2;                // 4 n-blocks
    const int g  = lane >> 2, tq = lane & 3;
    const int r0 = mb * 16 + g, r1 = r0 + 8;
    const int c0 = nb * 16 + 2 * tq;        // GEMM2 cols (tiles at c0, c0+8)
    const int lq = lane >> 3, lr = lane & 7;
    const int qm = (lq & 1) * 8, qk = (lq >> 1) * 8;

    // ---------------- per-thread RK4 state (C2-fragment layout) ----------------
    float x[8], bb[8];
    {
        const size_t gr0 = ((size_t)sb * N_DIM_ + node0 + r0) * 64;
        const size_t gr1 = ((size_t)sb * N_DIM_ + node0 + r1) * 64;
        #pragma unroll
        for (int t = 0; t < 2; t++) {
            const int c = c0 + 8 * t;
            x[t*4+0] = gS[gr0 + c]; x[t*4+1] = gS[gr0 + c + 1];
            x[t*4+2] = gS[gr1 + c]; x[t*4+3] = gS[gr1 + c + 1];
            bb[t*4+0] = gB[gr0 + c]     + gb2[c];
            bb[t*4+1] = gB[gr0 + c + 1] + gb2[c + 1];
            bb[t*4+2] = gB[gr1 + c]     + gb2[c];
            bb[t*4+3] = gB[gr1 + c + 1] + gb2[c + 1];
            *(u32*)(smc + O_YH + (r0 * 72 + c) * 2) = pk16(x[t*4+0], x[t*4+1]);
            *(u32*)(smc + O_YH + (r1 * 72 + c) * 2) = pk16(x[t*4+2], x[t*4+3]);
        }
    }
    __syncthreads();   // initial Y ready

    const float* cst = (const float*)(smc + O_CST);
    float accR[8], kk[8];

    for (int kb = 0; kb < 8; kb++) {
        const float dlt = ((const float*)(smc + O_DEL))[kb];
        #pragma unroll 1
        for (int ev = 0; ev < 8; ev++) {
            const int st = ev & 3;
            // ========== GEMM1: C1[64,256] = Y @ W1a, single n64 pass ==========
            float c1[8][4];
            #pragma unroll
            for (int nt = 0; nt < 8; nt++)
                #pragma unroll
                for (int j = 0; j < 4; j++) c1[nt][j] = 0.f;
            #pragma unroll
            for (int kt = 0; kt < 4; kt++) {
                const int k0 = kt * 16;
                u32 aoff = ((u32)((mb * 16 + qm + lr) * 72 + k0 + qk)) * 2;
                u32 a0, a1, a2, a3;
                ldsm_x4(a0, a1, a2, a3, smb + O_YH + aoff);
                #pragma unroll
                for (int half = 0; half < 4; half++) {
                    u32 boff = ((u32)((k0 + qm + lr) * 264
                                + nb * 64 + 16 * half + qk)) * 2;
                    u32 b0, b1, b2, b3;
                    ldsm_x4t(b0, b1, b2, b3, smb + O_W1H + boff);
                    mma16816(c1[2 * half],     a0, a1, a2, a3, b0, b1);
                    mma16816(c1[2 * half + 1], a0, a1, a2, a3, b2, b3);
                }
            }
            // epilogue: h = tanh(C1 + cst) -> H fp16
            #pragma unroll
            for (int nt = 0; nt < 8; nt++) {
                float* cc = c1[nt];
                const int col = nb * 64 + 8 * nt + 2 * tq;
                float2 cA = *(const float2*)(cst + r0 * 260 + col);
                float2 cB = *(const float2*)(cst + r1 * 260 + col);
                float t0 = tanh_fast(cc[0] + cA.x);
                float t1 = tanh_fast(cc[1] + cA.y);
                float t2 = tanh_fast(cc[2] + cB.x);
                float t3 = tanh_fast(cc[3] + cB.y);
                *(u32*)(smc + O_HH + (r0 * 264 + col) * 2) = pk16(t0, t1);
                *(u32*)(smc + O_HH + (r1 * 264 + col) * 2) = pk16(t2, t3);
            }
            __syncthreads();   // H ready; Y reads of this eval complete

            // ========== GEMM2: C2[64,64] = H @ W2 ==========
            float c2[2][4];
            #pragma unroll
            for (int t = 0; t < 2; t++)
                #pragma unroll
                for (int j = 0; j < 4; j++) c2[t][j] = 0.f;
            #pragma unroll 4
            for (int kt = 0; kt < 16; kt++) {
                const int k0 = kt * 16;
                u32 aoff = ((u32)((mb * 16 + qm + lr) * 264 + k0 + qk)) * 2;
                u32 a0, a1, a2, a3;
                ldsm_x4(a0, a1, a2, a3, smb + O_HH + aoff);
                u32 boff = ((u32)((k0 + qm + lr) * 72 + nb * 16 + qk)) * 2;
                u32 b0, b1, b2, b3;
                ldsm_x4t(b0, b1, b2, b3, smb + O_W2H + boff);
                mma16816(c2[0], a0, a1, a2, a3, b0, b1);
                mma16816(c2[1], a0, a1, a2, a3, b2, b3);
            }
            // ========== RK4 update ==========
            #pragma unroll
            for (int t = 0; t < 2; t++)
                #pragma unroll
                for (int j = 0; j < 4; j++)
                    kk[t*4+j] = (c2[t][j] + bb[t*4+j]) * dlt;
            float y[8];
            if (st == 0) {
                #pragma unroll
                for (int j = 0; j < 8; j++) { accR[j] = kk[j]; y[j] = x[j] + 0.25f * kk[j]; }
            } else if (st == 1) {
                #pragma unroll
                for (int j = 0; j < 8; j++) { accR[j] += 2.f * kk[j]; y[j] = x[j] + 0.25f * kk[j]; }
            } else if (st == 2) {
                #pragma unroll
                for (int j = 0; j < 8; j++) { accR[j] += 2.f * kk[j]; y[j] = x[j] + 0.5f * kk[j]; }
            } else {
                #pragma unroll
                for (int j = 0; j < 8; j++) { accR[j] += kk[j]; x[j] += (1.0f / 12.0f) * accR[j]; y[j] = x[j]; }
            }
            #pragma unroll
            for (int t = 0; t < 2; t++) {
                const int c = c0 + 8 * t;
                *(u32*)(smc + O_YH + (r0 * 72 + c) * 2) = pk16(y[t*4+0], y[t*4+1]);
                *(u32*)(smc + O_YH + (r1 * 72 + c) * 2) = pk16(y[t*4+2], y[t*4+3]);
            }
            if (ev == 7) {   // end of block-step: write output state
                const size_t ob = ((size_t)(s_i * 64 + b_i * 8 + kb) * N_DIM_ + node0);
                #pragma unroll
                for (int t = 0; t < 2; t++) {
                    const int c = c0 + 8 * t;
                    *(float2*)(gOut + (ob + r0) * 64 + c) = make_float2(x[t*4+0], x[t*4+1]);
                    *(float2*)(gOut + (ob + r1) * 64 + c) = make_float2(x[t*4+2], x[t*4+3]);
                }
            }
            __syncthreads();   // Y ready for next eval; H reads complete
        }
    }
}

extern "C" void kernel_launch(void* const* d_in, const int* in_sizes, int n_in,
                              void* d_out, int out_size) {
    (void)in_sizes; (void)n_in; (void)out_size;
    const float* s   = (const float*)d_in[0];
    const float* t   = (const float*)d_in[1];
    const float* Phi = (const float*)d_in[2];
    const float* b   = (const float*)d_in[3];
    const float* W1  = (const float*)d_in[4];
    const float* b1  = (const float*)d_in[5];
    const float* W2  = (const float*)d_in[6];
    const float* b2  = (const float*)d_in[7];
    cudaFuncSetAttribute(ode_f16s, cudaFuncAttributeMaxDynamicSharedMemorySize, SMEM_BYTES);
    ode_f16s<<<512, NTHREADS, SMEM_BYTES>>>(s, t, Phi, b, W1, b1, W2, b2, (float*)d_out);
}

// round 17
// speedup vs baseline: 5.9487x; 1.1698x over previous
#include <cuda_runtime.h>
#include <cuda_fp16.h>

#define NTHREADS 512
#define TN 64
#define N_DIM_ 2048

// ---- SMEM byte offsets ----
#define O_W1H 0          // fp16 [64 k][264]  W1a          33792
#define O_W2H 33792      // fp16 [256 k][72]  W2           36864
#define O_YH  70656      // fp16 [64 n][72]                 9216  (init overlay: f32 Phi 8KB)
#define O_HH  79872      // fp16 [64 n][264]               33792  (init overlay: f32 W1p 32KB)
#define O_CST 113664     // f32  [64 n][260]               66560
#define O_DEL 180224     // f32 [8]
#define SMEM_BYTES 180256

typedef unsigned int u32;

__device__ __forceinline__ u32 cvsm(const void* p) {
    u32 a; asm("{.reg .u64 t; cvta.to.shared.u64 t,%1; cvt.u32.u64 %0,t;}"
               : "=r"(a) : "l"(p)); return a;
}
__device__ __forceinline__ void ldsm_x4(u32& r0, u32& r1, u32& r2, u32& r3, u32 a) {
    asm volatile("ldmatrix.sync.aligned.m8n8.x4.shared.b16 {%0,%1,%2,%3},[%4];"
                 : "=r"(r0), "=r"(r1), "=r"(r2), "=r"(r3) : "r"(a));
}
__device__ __forceinline__ void ldsm_x4t(u32& r0, u32& r1, u32& r2, u32& r3, u32 a) {
    asm volatile("ldmatrix.sync.aligned.m8n8.x4.trans.shared.b16 {%0,%1,%2,%3},[%4];"
                 : "=r"(r0), "=r"(r1), "=r"(r2), "=r"(r3) : "r"(a));
}
__device__ __forceinline__ void mma16816(float* c, u32 a0, u32 a1, u32 a2, u32 a3,
                                         u32 b0, u32 b1) {
    asm volatile("mma.sync.aligned.m16n8k16.row.col.f32.f16.f16.f32 "
                 "{%0,%1,%2,%3},{%4,%5,%6,%7},{%8,%9},{%0,%1,%2,%3};"
                 : "+f"(c[0]), "+f"(c[1]), "+f"(c[2]), "+f"(c[3])
                 : "r"(a0), "r"(a1), "r"(a2), "r"(a3), "r"(b0), "r"(b1));
}
__device__ __forceinline__ float tanh_apx(float x) {
    float y; asm("tanh.approx.f32 %0, %1;" : "=f"(y) : "f"(x)); return y;
}
union HU { __half2 h; u32 u; };
__device__ __forceinline__ u32 pk16(float v0, float v1) {
    HU h; h.h = __floats2half2_rn(v0, v1); return h.u;
}
#define GBAR(id) asm volatile("bar.sync %0, 128;" :: "r"(id) : "memory")

extern __shared__ char smc[];

__global__ void __launch_bounds__(NTHREADS, 1)
ode_f16g(const float* __restrict__ gS,  const float* __restrict__ gT,
         const float* __restrict__ gPhi, const float* __restrict__ gB,
         const float* __restrict__ gW1, const float* __restrict__ gb1,
         const float* __restrict__ gW2, const float* __restrict__ gb2,
         float* __restrict__ gOut)
{
    const int tid  = threadIdx.x;
    const int wid  = tid >> 5, lane = tid & 31;
    const int sb   = blockIdx.x >> 5;        // 16 (s,b)
    const int tile = blockIdx.x & 31;        // 32 tiles of 64 nodes
    const int node0 = tile * TN;
    const int s_i = sb >> 3, b_i = sb & 7;
    const u32 smb = cvsm(smc);

    // ---------------- init phase 1: weight conversion + staging ----------------
    for (int i = tid; i < 64 * 256; i += NTHREADS) {        // W1a -> fp16 [k][264]
        int k = i >> 8, n = i & 255;
        *(__half*)(smc + O_W1H + (k * 264 + n) * 2) = __float2half(gW1[k * 256 + n]);
    }
    for (int i = tid; i < 256 * 64; i += NTHREADS) {        // W2 -> fp16 [k][72]
        int k = i >> 6, d = i & 63;
        *(__half*)(smc + O_W2H + (k * 72 + d) * 2) = __float2half(gW2[k * 64 + d]);
    }
    {   // W1p rows 64..95 staged f32 [q][256] at O_HH; Phi f32 [64][32] at O_YH
        float* wp = (float*)(smc + O_HH);
        for (int i = tid; i < 32 * 256; i += NTHREADS) wp[i] = gW1[64 * 256 + i];
        float* ph = (float*)(smc + O_YH);
        const size_t pbase = ((size_t)sb * N_DIM_ + node0) * 32;
        for (int i = tid; i < TN * 32; i += NTHREADS) ph[i] = gPhi[pbase + i];
    }
    if (tid < 8)
        ((float*)(smc + O_DEL))[tid] = gT[sb * 9 + tid + 1] - gT[sb * 9 + tid];
    __syncthreads();

    // ---------------- init phase 2: CST = Phi @ W1p + b1  (f32 [64][260]) ------
    {
        const int n    = tid >> 3;
        const int cgrp = tid & 7;
        const float* Ph = (const float*)(smc + O_YH) + n * 32;
        const float* Ws = (const float*)(smc + O_HH);
        float* cst = (float*)(smc + O_CST);
        #pragma unroll
        for (int ch = 0; ch < 2; ch++) {
            const int c0 = cgrp * 32 + ch * 16;
            float acc[16];
            #pragma unroll
            for (int j = 0; j < 16; j++) acc[j] = gb1[c0 + j];
            #pragma unroll 4
            for (int q = 0; q < 32; q++) {
                float p = Ph[q];
                #pragma unroll
                for (int jj = 0; jj < 4; jj++) {
                    float4 w = *(const float4*)(Ws + q * 256 + c0 + 4 * jj);
                    acc[4*jj]   += p * w.x; acc[4*jj+1] += p * w.y;
                    acc[4*jj+2] += p * w.z; acc[4*jj+3] += p * w.w;
                }
            }
            #pragma unroll
            for (int jj = 0; jj < 4; jj++)
                *(float4*)(cst + n * 260 + c0 + 4 * jj)
                    = make_float4(acc[4*jj], acc[4*jj+1], acc[4*jj+2], acc[4*jj+3]);
        }
    }
    __syncthreads();   // CST done; staging dead

    // ---------------- warp / thread tile mapping ----------------
    const int mb = wid & 3;                 // m-group: 4 indep 128-thread pipelines
    const int nb = wid >> 2;
    const int g  = lane >> 2, tq = lane & 3;
    const int r0 = mb * 16 + g, r1 = r0 + 8;
    const int c0 = nb * 16 + 2 * tq;
    const int lq = lane >> 3, lr = lane & 7;
    const int qm = (lq & 1) * 8, qk = (lq >> 1) * 8;
    const int barid = 1 + mb;

    // ---------------- per-thread RK4 state (C2-fragment layout) ----------------
    float x[8], bb[8];
    {
        const size_t gr0 = ((size_t)sb * N_DIM_ + node0 + r0) * 64;
        const size_t gr1 = ((size_t)sb * N_DIM_ + node0 + r1) * 64;
        #pragma unroll
        for (int t = 0; t < 2; t++) {
            const int c = c0 + 8 * t;
            x[t*4+0] = gS[gr0 + c]; x[t*4+1] = gS[gr0 + c + 1];
            x[t*4+2] = gS[gr1 + c]; x[t*4+3] = gS[gr1 + c + 1];
            bb[t*4+0] = gB[gr0 + c]     + gb2[c];
            bb[t*4+1] = gB[gr0 + c + 1] + gb2[c + 1];
            bb[t*4+2] = gB[gr1 + c]     + gb2[c];
            bb[t*4+3] = gB[gr1 + c + 1] + gb2[c + 1];
            *(u32*)(smc + O_YH + (r0 * 72 + c) * 2) = pk16(x[t*4+0], x[t*4+1]);
            *(u32*)(smc + O_YH + (r1 * 72 + c) * 2) = pk16(x[t*4+2], x[t*4+3]);
        }
    }
    __syncthreads();   // initial Y ready everywhere

    const float* cst = (const float*)(smc + O_CST);
    float accR[8], kk[8];

    for (int kb = 0; kb < 8; kb++) {
        const float dlt = ((const float*)(smc + O_DEL))[kb];
        #pragma unroll 1
        for (int ev = 0; ev < 8; ev++) {
            const int st = ev & 3;
            // ========== GEMM1: C1[16,256] per group = Y @ W1a ==========
            float c1[8][4];
            #pragma unroll
            for (int nt = 0; nt < 8; nt++)
                #pragma unroll
                for (int j = 0; j < 4; j++) c1[nt][j] = 0.f;
            #pragma unroll
            for (int kt = 0; kt < 4; kt++) {
                const int k0 = kt * 16;
                u32 aoff = ((u32)((mb * 16 + qm + lr) * 72 + k0 + qk)) * 2;
                u32 a0, a1, a2, a3;
                ldsm_x4(a0, a1, a2, a3, smb + O_YH + aoff);
                #pragma unroll
                for (int half = 0; half < 4; half++) {
                    u32 boff = ((u32)((k0 + qm + lr) * 264
                                + nb * 64 + 16 * half + qk)) * 2;
                    u32 b0, b1, b2, b3;
                    ldsm_x4t(b0, b1, b2, b3, smb + O_W1H + boff);
                    mma16816(c1[2 * half],     a0, a1, a2, a3, b0, b1);
                    mma16816(c1[2 * half + 1], a0, a1, a2, a3, b2, b3);
                }
            }
            // epilogue: h = tanh(C1 + cst) -> H fp16
            #pragma unroll
            for (int nt = 0; nt < 8; nt++) {
                float* cc = c1[nt];
                const int col = nb * 64 + 8 * nt + 2 * tq;
                float2 cA = *(const float2*)(cst + r0 * 260 + col);
                float2 cB = *(const float2*)(cst + r1 * 260 + col);
                float t0 = tanh_apx(cc[0] + cA.x);
                float t1 = tanh_apx(cc[1] + cA.y);
                float t2 = tanh_apx(cc[2] + cB.x);
                float t3 = tanh_apx(cc[3] + cB.y);
                *(u32*)(smc + O_HH + (r0 * 264 + col) * 2) = pk16(t0, t1);
                *(u32*)(smc + O_HH + (r1 * 264 + col) * 2) = pk16(t2, t3);
            }
            GBAR(barid);   // group: H rows [mb*16, mb*16+16) ready; Y reads done

            // ========== GEMM2: C2[16,64] per group = H @ W2 ==========
            float c2[2][4];
            #pragma unroll
            for (int t = 0; t < 2; t++)
                #pragma unroll
                for (int j = 0; j < 4; j++) c2[t][j] = 0.f;
            #pragma unroll 4
            for (int kt = 0; kt < 16; kt++) {
                const int k0 = kt * 16;
                u32 aoff = ((u32)((mb * 16 + qm + lr) * 264 + k0 + qk)) * 2;
                u32 a0, a1, a2, a3;
                ldsm_x4(a0, a1, a2, a3, smb + O_HH + aoff);
                u32 boff = ((u32)((k0 + qm + lr) * 72 + nb * 16 + qk)) * 2;
                u32 b0, b1, b2, b3;
                ldsm_x4t(b0, b1, b2, b3, smb + O_W2H + boff);
                mma16816(c2[0], a0, a1, a2, a3, b0, b1);
                mma16816(c2[1], a0, a1, a2, a3, b2, b3);
            }
            // ========== RK4 update ==========
            #pragma unroll
            for (int t = 0; t < 2; t++)
                #pragma unroll
                for (int j = 0; j < 4; j++)
                    kk[t*4+j] = (c2[t][j] + bb[t*4+j]) * dlt;
            float y[8];
            if (st == 0) {
                #pragma unroll
                for (int j = 0; j < 8; j++) { accR[j] = kk[j]; y[j] = x[j] + 0.25f * kk[j]; }
            } else if (st == 1) {
                #pragma unroll
                for (int j = 0; j < 8; j++) { accR[j] += 2.f * kk[j]; y[j] = x[j] + 0.25f * kk[j]; }
            } else if (st == 2) {
                #pragma unroll
                for (int j = 0; j < 8; j++) { accR[j] += 2.f * kk[j]; y[j] = x[j] + 0.5f * kk[j]; }
            } else {
                #pragma unroll
                for (int j = 0; j < 8; j++) { accR[j] += kk[j]; x[j] += (1.0f / 12.0f) * accR[j]; y[j] = x[j]; }
            }
            #pragma unroll
            for (int t = 0; t < 2; t++) {
                const int c = c0 + 8 * t;
                *(u32*)(smc + O_YH + (r0 * 72 + c) * 2) = pk16(y[t*4+0], y[t*4+1]);
                *(u32*)(smc + O_YH + (r1 * 72 + c) * 2) = pk16(y[t*4+2], y[t*4+3]);
            }
            if (ev == 7) {   // end of block-step: write output state
                const size_t ob = ((size_t)(s_i * 64 + b_i * 8 + kb) * N_DIM_ + node0);
                #pragma unroll
                for (int t = 0; t < 2; t++) {
                    const int c = c0 + 8 * t;
                    *(float2*)(gOut + (ob + r0) * 64 + c) = make_float2(x[t*4+0], x[t*4+1]);
                    *(float2*)(gOut + (ob + r1) * 64 + c) = make_float2(x[t*4+2], x[t*4+3]);
                }
            }
            GBAR(barid);   // group: Y rows ready for next eval; H reads done
        }
    }
}

extern "C" void kernel_launch(void* const* d_in, const int* in_sizes, int n_in,
                              void* d_out, int out_size) {
    (void)in_sizes; (void)n_in; (void)out_size;
    const float* s   = (const float*)d_in[0];
    const float* t   = (const float*)d_in[1];
    const float* Phi = (const float*)d_in[2];
    const float* b   = (const float*)d_in[3];
    const float* W1  = (const float*)d_in[4];
    const float* b1  = (const float*)d_in[5];
    const float* W2  = (const float*)d_in[6];
    const float* b2  = (const float*)d_in[7];
    cudaFuncSetAttribute(ode_f16g, cudaFuncAttributeMaxDynamicSharedMemorySize, SMEM_BYTES);
    ode_f16g<<<512, NTHREADS, SMEM_BYTES>>>(s, t, Phi, b, W1, b1, W2, b2, (float*)d_out);
}